// round 2
// baseline (speedup 1.0000x reference)
#include <cuda_runtime.h>

// out[b,o] = sum_i w_out[o,i] * sin(x[b,i]*w_sin[o,i] + b_sin[o,i]) + b_out[o]
// B=2048, I=256, O=512.
// weight: [O][I][2]  (w_out = [..][0], w_sin = [..][1])  -> load as float2
// bias:   [O][I+1]   (b_sin = [o][0..I), b_out = [o][I])

#define B_DIM 2048
#define I_DIM 256
#define O_DIM 512

#define BM 64   // b-tile per block
#define BO 32   // o-tile per block
#define KC 64   // i-chunk

__global__ __launch_bounds__(256, 4)
void trigo_linear_kernel(const float* __restrict__ x,
                         const float* __restrict__ weight,
                         const float* __restrict__ bias,
                         float* __restrict__ out)
{
    __shared__ float  xs[BM][KC];          // 16 KB, inner reads are warp-broadcast
    __shared__ float2 ws[BO][KC + 1];      // 16.6 KB, +1 pad -> conflict-free o-strided reads
    __shared__ float  bs[BO][KC + 1];      // 8.3 KB,  +1 pad

    const int tid     = threadIdx.x;
    const int o_local = tid & 31;          // lane -> o within tile
    const int bg      = tid >> 5;          // warp -> b-group (8 b's each)
    const int b_tile  = blockIdx.x * BM;
    const int o_tile  = blockIdx.y * BO;
    const int o       = o_tile + o_local;

    const float2* __restrict__ wg = (const float2*)weight;  // [O][I] float2

    // hoisted base pointers for the inner loop
    const float* xrow0 = &xs[bg * 8][0];   // rows bg*8 .. bg*8+7, stride KC floats

    float acc[8];
    #pragma unroll
    for (int k = 0; k < 8; k++) acc[k] = 0.0f;

    for (int c = 0; c < I_DIM; c += KC) {
        __syncthreads();   // protect smem from previous chunk's readers

        // ---- stage x chunk: 64 rows x 64 cols as float4 (1024 float4 / 256 thr = 4 each)
        {
            const int nvec = BM * KC / 4;                    // 1024
            for (int t = tid; t < nvec; t += 256) {
                int row = t >> 4;                            // /16 float4 per row
                int c4  = t & 15;
                float4 v = *(const float4*)&x[(size_t)(b_tile + row) * I_DIM + c + c4 * 4];
                *(float4*)&xs[row][c4 * 4] = v;
            }
        }
        // ---- stage weight chunk: 32 o x 64 i float2 (2048 / 256 = 8 each, coalesced in i)
        {
            for (int t = tid; t < BO * KC; t += 256) {
                int ol = t >> 6;                             // /KC
                int il = t & (KC - 1);
                ws[ol][il] = wg[(size_t)(o_tile + ol) * I_DIM + c + il];
            }
        }
        // ---- stage b_sin chunk: 32 o x 64 i floats
        {
            for (int t = tid; t < BO * KC; t += 256) {
                int ol = t >> 6;
                int il = t & (KC - 1);
                bs[ol][il] = bias[(size_t)(o_tile + ol) * (I_DIM + 1) + c + il];
            }
        }
        __syncthreads();

        // ---- compute: per i, 1 LDS.64 + 1 LDS.32 (o-strided, conflict-free),
        //      then 8 broadcast xs reads feeding 8 independent sin chains.
        #pragma unroll 4
        for (int i = 0; i < KC; i++) {
            float2 w   = ws[o_local][i];   // w.x = w_out, w.y = w_sin
            float  bsv = bs[o_local][i];
            #pragma unroll
            for (int k = 0; k < 8; k++) {
                float xv = xrow0[k * KC + i];   // warp-broadcast read
                float s  = __sinf(fmaf(xv, w.y, bsv));
                acc[k]   = fmaf(w.x, s, acc[k]);
            }
        }
    }

    const float b_out = bias[(size_t)o * (I_DIM + 1) + I_DIM];

    // warp lanes write consecutive o -> coalesced 128B rows
    #pragma unroll
    for (int k = 0; k < 8; k++) {
        out[(size_t)(b_tile + bg * 8 + k) * O_DIM + o] = acc[k] + b_out;
    }
}

extern "C" void kernel_launch(void* const* d_in, const int* in_sizes, int n_in,
                              void* d_out, int out_size)
{
    const float* x      = (const float*)d_in[0];
    const float* weight = (const float*)d_in[1];
    const float* bias   = (const float*)d_in[2];
    float* out          = (float*)d_out;

    dim3 grid(B_DIM / BM, O_DIM / BO);   // 32 x 16 = 512 blocks
    trigo_linear_kernel<<<grid, 256>>>(x, weight, bias, out);
}